// round 3
// baseline (speedup 1.0000x reference)
#include <cuda_runtime.h>

#define N_VOX 400000
#define C 32
#define K_TAPS 27
#define FULL 0xffffffffu

// Intermediate activation buffer (conv1 -> conv2). Static device array: no allocation.
__device__ float g_h[(size_t)N_VOX * C];

// One warp per voxel, lane = output channel.
// Computes: out[i] = act( LN( sum_k x[nbr[k][i]] @ W[k] ) [ + resid[i] ] )
//   RESID=false:  relu(LN(conv))               (block 1)
//   RESID=true :  relu(LN(conv) + resid)       (block 2 + residual)
template <bool RESID>
__global__ void __launch_bounds__(256)
conv_ln_kernel(const float* __restrict__ in,
               const int*   __restrict__ nbr,
               const float* __restrict__ W,
               const float* __restrict__ gamma,
               const float* __restrict__ beta,
               const float* __restrict__ resid,
               float*       __restrict__ out)
{
    const int warp = blockIdx.x * (blockDim.x >> 5) + (threadIdx.x >> 5);
    const int lane = threadIdx.x & 31;
    if (warp >= N_VOX) return;
    const int i = warp;

    // Preload all 27 neighbor indices into lanes 0..26 (one LDG), broadcast per tap.
    int idx_l = (lane < K_TAPS) ? nbr[lane * N_VOX + i] : -1;

    // Two accumulators to shorten the FMA dependence chain.
    float acc0 = 0.0f, acc1 = 0.0f;

    #pragma unroll 1
    for (int k = 0; k < K_TAPS; ++k) {
        const int idx = __shfl_sync(FULL, idx_l, k);   // warp-uniform
        if (idx < 0) continue;                          // skip inactive taps (~91% of them)

        const float xv = in[idx * C + lane];            // coalesced 128B gather
        const float* Wk = W + k * (C * C) + lane;       // column `lane` of W[k]

        #pragma unroll
        for (int cin = 0; cin < C; cin += 2) {
            acc0 = fmaf(__shfl_sync(FULL, xv, cin),     Wk[cin * C],       acc0);
            acc1 = fmaf(__shfl_sync(FULL, xv, cin + 1), Wk[(cin + 1) * C], acc1);
        }
    }

    float h = acc0 + acc1;

    // LayerNorm across the 32 lanes (channels) via butterfly reduction.
    float s = h, s2 = h * h;
    #pragma unroll
    for (int o = 16; o; o >>= 1) {
        s  += __shfl_xor_sync(FULL, s,  o);
        s2 += __shfl_xor_sync(FULL, s2, o);
    }
    const float mu  = s  * (1.0f / 32.0f);
    const float var = s2 * (1.0f / 32.0f) - mu * mu;
    float y = (h - mu) * rsqrtf(var + 1e-6f) * gamma[lane] + beta[lane];

    if (RESID) y += resid[i * C + lane];
    out[i * C + lane] = fmaxf(y, 0.0f);
}

extern "C" void kernel_launch(void* const* d_in, const int* in_sizes, int n_in,
                              void* d_out, int out_size)
{
    const float* x   = (const float*)d_in[0];  // [N, 32]
    const int*   nbr = (const int*)  d_in[1];  // [27, N]
    const float* W1  = (const float*)d_in[2];  // [27, 32, 32]
    const float* g1  = (const float*)d_in[3];
    const float* b1  = (const float*)d_in[4];
    const float* W2  = (const float*)d_in[5];
    const float* g2  = (const float*)d_in[6];
    const float* b2  = (const float*)d_in[7];
    float* out = (float*)d_out;

    float* h_buf = nullptr;
    cudaGetSymbolAddress((void**)&h_buf, g_h);

    // 8 warps (voxels) per 256-thread block.
    const int warps_per_block = 256 / 32;
    const int grid = (N_VOX + warps_per_block - 1) / warps_per_block;

    // Block 1: h = relu(LN(sparse_conv(x, W1)))
    conv_ln_kernel<false><<<grid, 256>>>(x, nbr, W1, g1, b1, nullptr, h_buf);
    // Block 2: out = relu(LN(sparse_conv(h, W2)) + x)
    conv_ln_kernel<true ><<<grid, 256>>>(h_buf, nbr, W2, g2, b2, x, out);
}

// round 4
// speedup vs baseline: 1.0782x; 1.0782x over previous
#include <cuda_runtime.h>

#define N_VOX 400000
#define C 32
#define K_TAPS 27
#define FULL 0xffffffffu
#define W_PITCH 36                                  // floats per (k,cout) row: 16B-aligned, conflict-free LDS.128
#define SMEM_W_BYTES (K_TAPS * 32 * W_PITCH * 4)    // 124,416 B

// Static device scratch (no allocations allowed).
__device__ float g_h[(size_t)N_VOX * C];            // conv1 output
__device__ int   g_nbrt[(size_t)N_VOX * 32];        // transposed neighbor table, padded to 32

// ---------------------------------------------------------------------------
// Transpose nbr[K,N] -> nbr_t[N,32] (pad lanes 27..31 with -1) so each voxel's
// 27 indices are one coalesced 128B line instead of 27 wavefronts.
// ---------------------------------------------------------------------------
__global__ void __launch_bounds__(1024)
transpose_nbr_kernel(const int* __restrict__ nbr, int* __restrict__ nbrt)
{
    __shared__ int tile[32][33];
    const int i0 = blockIdx.x * 32;
    const int x = threadIdx.x, y = threadIdx.y;
    const int i = i0 + x;
    tile[y][x] = (y < K_TAPS && i < N_VOX) ? nbr[y * N_VOX + i] : -1;
    __syncthreads();
    const int iv = i0 + y;
    if (iv < N_VOX) nbrt[(size_t)iv * 32 + x] = tile[x][y];
}

// ---------------------------------------------------------------------------
// Fused sparse-conv + LayerNorm + activation. One warp per voxel, lane = cout.
// W lives in smem transposed [k][cout][cin] with pitch 36 -> 8x LDS.128 per tap.
// x row read via uniform LDG.128 broadcasts -> 8 loads per tap, no shuffles.
// Active taps enumerated with ballot/ffs (avg ~2.5 of 27).
// ---------------------------------------------------------------------------
template <bool RESID>
__global__ void __launch_bounds__(1024, 1)
conv_ln_kernel(const float* __restrict__ in,
               const int*   __restrict__ nbrt,
               const float* __restrict__ W,      // [27,32,32] (cin-major rows of cout)
               const float* __restrict__ gamma,
               const float* __restrict__ beta,
               const float* __restrict__ resid,
               float*       __restrict__ out)
{
    extern __shared__ float ws[];

    // Cooperative W load + transpose: ws[(k*32+cout)*36 + cin] = W[k][cin][cout]
    for (int t = threadIdx.x; t < K_TAPS * 1024; t += blockDim.x) {
        const int k = t >> 10, r = t & 1023, cin = r >> 5, cout = r & 31;
        ws[(k * 32 + cout) * W_PITCH + cin] = W[t];
    }
    __syncthreads();

    const int lane       = threadIdx.x & 31;
    const int warp_gid   = (blockIdx.x * blockDim.x + threadIdx.x) >> 5;
    const int warp_total = (gridDim.x * blockDim.x) >> 5;
    const float gm = gamma[lane];
    const float bt = beta[lane];

    for (int i = warp_gid; i < N_VOX; i += warp_total) {
        const int idx_l = nbrt[(size_t)i * 32 + lane];   // one coalesced line; pad lanes = -1

        float acc0 = 0.0f, acc1 = 0.0f;
        unsigned m = __ballot_sync(FULL, idx_l >= 0);
        while (m) {
            const int k = __ffs(m) - 1;
            m &= m - 1;
            const int idx = __shfl_sync(FULL, idx_l, k);

            const float4* __restrict__ xr =
                reinterpret_cast<const float4*>(in + (size_t)idx * C);
            const float4* __restrict__ wr =
                reinterpret_cast<const float4*>(ws + (k * 32 + lane) * W_PITCH);

            #pragma unroll
            for (int c = 0; c < 8; c += 2) {
                const float4 xv0 = xr[c],     wv0 = wr[c];
                const float4 xv1 = xr[c + 1], wv1 = wr[c + 1];
                acc0 = fmaf(xv0.x, wv0.x, fmaf(xv0.y, wv0.y,
                       fmaf(xv0.z, wv0.z, fmaf(xv0.w, wv0.w, acc0))));
                acc1 = fmaf(xv1.x, wv1.x, fmaf(xv1.y, wv1.y,
                       fmaf(xv1.z, wv1.z, fmaf(xv1.w, wv1.w, acc1))));
            }
        }
        const float h = acc0 + acc1;

        // LayerNorm over the 32 channels (lanes).
        float s = h, s2 = h * h;
        #pragma unroll
        for (int o = 16; o; o >>= 1) {
            s  += __shfl_xor_sync(FULL, s,  o);
            s2 += __shfl_xor_sync(FULL, s2, o);
        }
        const float mu  = s  * 0.03125f;
        const float var = s2 * 0.03125f - mu * mu;
        float y = (h - mu) * rsqrtf(var + 1e-6f) * gm + bt;

        if (RESID) y += resid[(size_t)i * C + lane];
        out[(size_t)i * C + lane] = fmaxf(y, 0.0f);
    }
}

extern "C" void kernel_launch(void* const* d_in, const int* in_sizes, int n_in,
                              void* d_out, int out_size)
{
    const float* x   = (const float*)d_in[0];  // [N, 32]
    const int*   nbr = (const int*)  d_in[1];  // [27, N]
    const float* W1  = (const float*)d_in[2];  // [27, 32, 32]
    const float* g1  = (const float*)d_in[3];
    const float* b1  = (const float*)d_in[4];
    const float* W2  = (const float*)d_in[5];
    const float* g2  = (const float*)d_in[6];
    const float* b2  = (const float*)d_in[7];
    float* out = (float*)d_out;

    float* h_buf = nullptr;
    int*   nbrt  = nullptr;
    cudaGetSymbolAddress((void**)&h_buf, g_h);
    cudaGetSymbolAddress((void**)&nbrt,  g_nbrt);

    cudaFuncSetAttribute(conv_ln_kernel<false>,
                         cudaFuncAttributeMaxDynamicSharedMemorySize, SMEM_W_BYTES);
    cudaFuncSetAttribute(conv_ln_kernel<true>,
                         cudaFuncAttributeMaxDynamicSharedMemorySize, SMEM_W_BYTES);

    // 1) Transpose neighbor table (once per launch, deterministic).
    transpose_nbr_kernel<<<(N_VOX + 31) / 32, dim3(32, 32)>>>(nbr, nbrt);

    // 2) Block 1: h = relu(LN(conv(x, W1)))
    conv_ln_kernel<false><<<760, 1024, SMEM_W_BYTES>>>(x, nbrt, W1, g1, b1, nullptr, h_buf);

    // 3) Block 2: out = relu(LN(conv(h, W2)) + x)
    conv_ln_kernel<true ><<<760, 1024, SMEM_W_BYTES>>>(h_buf, nbrt, W2, g2, b2, x, out);
}

// round 5
// speedup vs baseline: 1.4044x; 1.3025x over previous
#include <cuda_runtime.h>
#include <cuda_fp16.h>

#define N_VOX 400000
#define C 32
#define K_TAPS 27
#define FULL 0xffffffffu

// W smem layout: half elements, row per (k,cout), pitch 40 halfs = 80B.
//  - 16B-aligned rows (uint4 loads legal)
//  - lanes l*80 mod 128 hit distinct bank groups -> conflict-free LDS.128
#define W_PITCH_H 40
#define SMEM_W_BYTES (K_TAPS * 32 * W_PITCH_H * 2)   // 69,120 B

// Static device scratch (no allocations allowed).
__device__ float g_h[(size_t)N_VOX * C];             // conv1 output
__device__ int   g_nbrt[(size_t)N_VOX * 32];         // transposed neighbor table

// ---------------------------------------------------------------------------
// Transpose nbr[K,N] -> nbr_t[N,32] (pad 27..31 with -1). 4 elements/thread
// for MLP=4 (prev version was latency-bound at 1 elem/thread).
// ---------------------------------------------------------------------------
__global__ void __launch_bounds__(256)
transpose_nbr_kernel(const int* __restrict__ nbr, int* __restrict__ nbrt)
{
    __shared__ int tile[32][33];
    const int i0 = blockIdx.x * 32;
    const int x = threadIdx.x, ty = threadIdx.y;          // 32 x 8
    const int i = i0 + x;

    int v[4];
    #pragma unroll
    for (int j = 0; j < 4; ++j) {
        const int k = ty + j * 8;
        v[j] = (k < K_TAPS && i < N_VOX) ? nbr[k * N_VOX + i] : -1;
    }
    #pragma unroll
    for (int j = 0; j < 4; ++j) tile[ty + j * 8][x] = v[j];
    __syncthreads();

    #pragma unroll
    for (int j = 0; j < 4; ++j) {
        const int iv = i0 + ty + j * 8;
        if (iv < N_VOX) nbrt[(size_t)iv * 32 + x] = tile[x][ty + j * 8];
    }
}

// ---------------------------------------------------------------------------
// Fused sparse-conv + LayerNorm + activation. One warp per voxel, lane = cout.
// W cached in smem as fp16, transposed [k][cout][cin] (pitch 80B):
//   4x LDS.128 per tap (was 8 fp32) -> half the smem-crossbar bytes.
// x rows via uniform LDG.128 broadcast; fp32 accumulation throughout.
// Active taps (avg ~2.5/27) enumerated with ballot/ffs.
// ---------------------------------------------------------------------------
template <bool RESID>
__global__ void __launch_bounds__(1024, 1)
conv_ln_kernel(const float* __restrict__ in,
               const int*   __restrict__ nbrt,
               const float* __restrict__ W,      // [27,32,32] fp32 (cin-major)
               const float* __restrict__ gamma,
               const float* __restrict__ beta,
               const float* __restrict__ resid,
               float*       __restrict__ out)
{
    extern __shared__ __half ws[];

    // Preload + convert + transpose: ws[(k*32+cout)*40 + cin] = half(W[k][cin][cout])
    for (int t = threadIdx.x; t < K_TAPS * 1024; t += blockDim.x) {
        const int k = t >> 10, r = t & 1023, cin = r >> 5, cout = r & 31;
        ws[(k * 32 + cout) * W_PITCH_H + cin] = __float2half_rn(W[t]);
    }
    __syncthreads();

    const int lane       = threadIdx.x & 31;
    const int warp_gid   = (blockIdx.x * blockDim.x + threadIdx.x) >> 5;
    const int warp_total = (gridDim.x * blockDim.x) >> 5;
    const float gm = gamma[lane];
    const float bt = beta[lane];

    for (int i = warp_gid; i < N_VOX; i += warp_total) {
        const int idx_l = nbrt[(size_t)i * 32 + lane];   // one coalesced line

        float acc0 = 0.0f, acc1 = 0.0f;
        unsigned m = __ballot_sync(FULL, idx_l >= 0);
        while (m) {
            const int k = __ffs(m) - 1;
            m &= m - 1;
            const int idx = __shfl_sync(FULL, idx_l, k);

            const float4* __restrict__ xr =
                reinterpret_cast<const float4*>(in + (size_t)idx * C);
            const uint4* __restrict__ wr =
                reinterpret_cast<const uint4*>(ws + (k * 32 + lane) * W_PITCH_H);

            #pragma unroll
            for (int c = 0; c < 4; ++c) {
                uint4 w4 = wr[c];                        // 8 halfs = 8 cin weights
                const float2 f0 = __half22float2(*reinterpret_cast<__half2*>(&w4.x));
                const float2 f1 = __half22float2(*reinterpret_cast<__half2*>(&w4.y));
                const float2 f2 = __half22float2(*reinterpret_cast<__half2*>(&w4.z));
                const float2 f3 = __half22float2(*reinterpret_cast<__half2*>(&w4.w));
                const float4 xa = xr[2 * c];
                const float4 xb = xr[2 * c + 1];
                acc0 = fmaf(xa.x, f0.x, acc0);  acc1 = fmaf(xa.y, f0.y, acc1);
                acc0 = fmaf(xa.z, f1.x, acc0);  acc1 = fmaf(xa.w, f1.y, acc1);
                acc0 = fmaf(xb.x, f2.x, acc0);  acc1 = fmaf(xb.y, f2.y, acc1);
                acc0 = fmaf(xb.z, f3.x, acc0);  acc1 = fmaf(xb.w, f3.y, acc1);
            }
        }
        const float h = acc0 + acc1;

        // LayerNorm over the 32 channels (lanes).
        float s = h, s2 = h * h;
        #pragma unroll
        for (int o = 16; o; o >>= 1) {
            s  += __shfl_xor_sync(FULL, s,  o);
            s2 += __shfl_xor_sync(FULL, s2, o);
        }
        const float mu  = s  * 0.03125f;
        const float var = s2 * 0.03125f - mu * mu;
        float y = (h - mu) * rsqrtf(var + 1e-6f) * gm + bt;

        if (RESID) y += resid[(size_t)i * C + lane];
        out[(size_t)i * C + lane] = fmaxf(y, 0.0f);
    }
}

extern "C" void kernel_launch(void* const* d_in, const int* in_sizes, int n_in,
                              void* d_out, int out_size)
{
    const float* x   = (const float*)d_in[0];  // [N, 32]
    const int*   nbr = (const int*)  d_in[1];  // [27, N]
    const float* W1  = (const float*)d_in[2];  // [27, 32, 32]
    const float* g1  = (const float*)d_in[3];
    const float* b1  = (const float*)d_in[4];
    const float* W2  = (const float*)d_in[5];
    const float* g2  = (const float*)d_in[6];
    const float* b2  = (const float*)d_in[7];
    float* out = (float*)d_out;

    float* h_buf = nullptr;
    int*   nbrt  = nullptr;
    cudaGetSymbolAddress((void**)&h_buf, g_h);
    cudaGetSymbolAddress((void**)&nbrt,  g_nbrt);

    cudaFuncSetAttribute(conv_ln_kernel<false>,
                         cudaFuncAttributeMaxDynamicSharedMemorySize, SMEM_W_BYTES);
    cudaFuncSetAttribute(conv_ln_kernel<true>,
                         cudaFuncAttributeMaxDynamicSharedMemorySize, SMEM_W_BYTES);

    // 1) Transpose neighbor table.
    transpose_nbr_kernel<<<(N_VOX + 31) / 32, dim3(32, 8)>>>(nbr, nbrt);

    // 2) Block 1: h = relu(LN(conv(x, W1)))
    conv_ln_kernel<false><<<296, 1024, SMEM_W_BYTES>>>(x, nbrt, W1, g1, b1, nullptr, h_buf);

    // 3) Block 2: out = relu(LN(conv(h, W2)) + x)
    conv_ln_kernel<true ><<<296, 1024, SMEM_W_BYTES>>>(h_buf, nbrt, W2, g2, b2, x, out);
}